// round 13
// baseline (speedup 1.0000x reference)
#include <cuda_runtime.h>
#include <cuda_bf16.h>
#include <cstdint>
#include <cstddef>

// ---------------------------------------------------------------------------
// Problem constants
// ---------------------------------------------------------------------------
#define NIMG   2
#define CIN    64
#define HF     128
#define WF     128
#define NPIX   (HF*WF)        // 16384
#define HD     256
#define KCOL   (CIN*9)        // 576
#define HO     256
#define WO     256
#define NQ     (HO*WO)        // 65536
#define NROWS  (NIMG*4*NQ)    // 524288
#define NCF    512            // merged coef|freq channel count

// ---------------------------------------------------------------------------
// Scratch (device globals; allocation-free)
// ---------------------------------------------------------------------------
__device__ float g_col [(size_t)NIMG*NPIX*KCOL];   // im2col (tf32-rounded)
__device__ float g_cf  [(size_t)NIMG*NPIX*NCF];    // NHWC coef|freq (fp32) 64MB
__device__ float g_x   [(size_t)NROWS*HD];         // activations
__device__ float g_h   [(size_t)NROWS*HD];         // activations
__device__ float g_area[(size_t)NROWS];
__device__ float g_pred[2][(size_t)NROWS*3];       // per-n-half partial preds
__device__ float g_wr  [3*HD*HD + 2*HD*KCOL];      // tf32-rounded weights
__device__ float g_cfb [NCF];                      // concat conv bias (raw)

#define WR_W1    0
#define WR_W2    (HD*HD)
#define WR_W3    (2*HD*HD)
#define WR_CFW   (3*HD*HD)            // [512][576]: rows 0-255 coef, 256-511 freq

__device__ __forceinline__ uint32_t f2tf32(float f)
{
    uint32_t r;
    asm("cvt.rna.tf32.f32 %0, %1;" : "=r"(r) : "f"(f));
    return r;
}
__device__ __forceinline__ float roundtf(float f)
{
    return __uint_as_float(f2tf32(f));
}
__device__ __forceinline__ void cp16(uint32_t dst, const void* src)
{
    asm volatile("cp.async.ca.shared.global [%0], [%1], 16;" :: "r"(dst), "l"(src));
}

// ---------------------------------------------------------------------------
// k_prep: single launch that tf32-rounds all 5 weight matrices and builds the
// concatenated conv bias. (Single kernel so the layer-1 MLP GEMM lands in
// ncu's capture slot: prep, im2col, conv, conv, assemble, GEMM = launch #6.)
// Flat index map:
//   [0, 3*HD*HD)                     -> w1|w2|w3
//   [3*HD*HD, 3*HD*HD + HD*KCOL)     -> coef_w
//   [.., + 2*HD*KCOL)                -> freq_w
//   last NCF                         -> bias concat
// ---------------------------------------------------------------------------
#define PREP_TOTAL (3*HD*HD + 2*HD*KCOL + NCF)
__global__ void k_prep(const float* __restrict__ w1, const float* __restrict__ w2,
                       const float* __restrict__ w3, const float* __restrict__ cw,
                       const float* __restrict__ fw, const float* __restrict__ cb,
                       const float* __restrict__ fb)
{
    int i = blockIdx.x * blockDim.x + threadIdx.x;
    if (i >= PREP_TOTAL) return;
    if (i < 3*HD*HD + 2*HD*KCOL) {
        const float* src;
        int j = i;
        if (j < HD*HD)            { src = w1; }
        else if (j < 2*HD*HD)     { src = w2; j -= HD*HD; }
        else if (j < 3*HD*HD)     { src = w3; j -= 2*HD*HD; }
        else if (j < 3*HD*HD + HD*KCOL) { src = cw; j -= 3*HD*HD; }
        else                      { src = fw; j -= 3*HD*HD + HD*KCOL; }
        g_wr[i] = roundtf(src[j]);
    } else {
        int j = i - (3*HD*HD + 2*HD*KCOL);
        g_cfb[j] = (j < HD) ? cb[j] : fb[j - HD];
    }
}

// ---------------------------------------------------------------------------
// im2col: g_col[img][pix][ic*9 + ky*3 + kx], zero-padded 3x3, tf32-rounded
// ---------------------------------------------------------------------------
__global__ void k_im2col(const float* __restrict__ feat)
{
    size_t idx = (size_t)blockIdx.x * blockDim.x + threadIdx.x;
    const size_t total = (size_t)NIMG * NPIX * KCOL;
    if (idx >= total) return;
    int col = (int)(idx % KCOL);
    size_t pi = idx / KCOL;
    int pix = (int)(pi % NPIX);
    int img = (int)(pi / NPIX);
    int ic = col / 9;
    int k  = col % 9;
    int ky = k / 3, kx = k % 3;
    int y = pix / WF, x = pix % WF;
    int gy = y + ky - 1, gx = x + kx - 1;
    float v = 0.f;
    if ((unsigned)gy < (unsigned)HF && (unsigned)gx < (unsigned)WF)
        v = feat[(((size_t)img*CIN + ic)*HF + gy)*WF + gx];
    g_col[idx] = roundtf(v);
}

// ---------------------------------------------------------------------------
// GEMM config: BM=BN=128, BK=32, 256 threads, 8 warps (2x4), warp tile 64x32,
// mma m16n8k8. THIS ROUND: 3-stage cp.async ring, ONE __syncthreads per slab
// (isolated change vs R12's 2-stage/2-sync; everything else identical).
// ---------------------------------------------------------------------------
#define BK     32
#define SMROW  36                      // 32 data + 4 pad; banks (4r+c)%32 unique
#define SMBUF  (128*SMROW)             // floats per stage per matrix
#define NSTAGE 3
#define SMEM_GEMM_BYTES (2 * NSTAGE * SMBUF * 4)            // 110592 B
#define SMEM_W4_BYTES   (2 * NSTAGE * SMBUF * 4 + 2048)     // + s_pred[128][4]

// Mainloop macro. Produces acc[4][4][4]; uses names: A, B, m0, n0, tid,
// Asm, Bsm, wm, wn, lane. Requires nslab >= 2.
#define GEMM_MAINLOOP(Kval)                                                    \
    const int row  = tid >> 1;                                                 \
    const int half = tid & 1;                                                  \
    const float* Ap = A + (size_t)(m0 + row) * (Kval) + half*16;               \
    const float* Bp = B + (size_t)(n0 + row) * (Kval) + half*16;               \
    const uint32_t sA0 = (uint32_t)__cvta_generic_to_shared(Asm)               \
                       + (row*SMROW + half*16)*4;                              \
    const uint32_t sB0 = (uint32_t)__cvta_generic_to_shared(Bsm)               \
                       + (row*SMROW + half*16)*4;                              \
    const uint32_t stageb = SMBUF * 4;                                         \
    const int abase = (wm*64 + (lane>>2)) * SMROW + (lane & 3);                \
    const int bbase = (wn*32 + (lane>>2)) * SMROW + (lane & 3);                \
    _Pragma("unroll")                                                          \
    for (int p = 0; p < 2; p++) {                                              \
        const int ko = p * BK;                                                 \
        const uint32_t so = (uint32_t)p * stageb;                              \
        _Pragma("unroll")                                                      \
        for (int i = 0; i < 4; i++) cp16(sA0 + so + i*16, Ap + ko + i*4);      \
        _Pragma("unroll")                                                      \
        for (int i = 0; i < 4; i++) cp16(sB0 + so + i*16, Bp + ko + i*4);      \
        asm volatile("cp.async.commit_group;" ::: "memory");                   \
    }                                                                          \
    const int nslab = (Kval) / BK;                                             \
    int st = 0, st2 = 2;                                                       \
    for (int s = 0; s < nslab; s++) {                                          \
        if (s + 1 < nslab) asm volatile("cp.async.wait_group 1;" ::: "memory");\
        else               asm volatile("cp.async.wait_group 0;" ::: "memory");\
        __syncthreads();                                                       \
        if (s + 2 < nslab) {                                                   \
            const int ko = (s + 2) * BK;                                       \
            const uint32_t so = (uint32_t)st2 * stageb;                        \
            _Pragma("unroll")                                                  \
            for (int i = 0; i < 4; i++) cp16(sA0 + so + i*16, Ap + ko + i*4);  \
            _Pragma("unroll")                                                  \
            for (int i = 0; i < 4; i++) cp16(sB0 + so + i*16, Bp + ko + i*4);  \
            asm volatile("cp.async.commit_group;" ::: "memory");               \
        }                                                                      \
        const uint32_t* as = (const uint32_t*)(Asm + st*SMBUF);                \
        const uint32_t* bs = (const uint32_t*)(Bsm + st*SMBUF);                \
        _Pragma("unroll")                                                      \
        for (int ks = 0; ks < 4; ks++) {                                       \
            uint32_t af[4][4], bf[4][2];                                       \
            _Pragma("unroll")                                                  \
            for (int mt = 0; mt < 4; mt++) {                                   \
                const int o = abase + mt*(16*SMROW) + ks*8;                    \
                af[mt][0] = as[o];                                             \
                af[mt][1] = as[o + 8*SMROW];                                   \
                af[mt][2] = as[o + 4];                                         \
                af[mt][3] = as[o + 8*SMROW + 4];                               \
            }                                                                  \
            _Pragma("unroll")                                                  \
            for (int nt = 0; nt < 4; nt++) {                                   \
                const int o = bbase + nt*(8*SMROW) + ks*8;                     \
                bf[nt][0] = bs[o];                                             \
                bf[nt][1] = bs[o + 4];                                         \
            }                                                                  \
            _Pragma("unroll")                                                  \
            for (int mt = 0; mt < 4; mt++)                                     \
                _Pragma("unroll")                                              \
                for (int nt = 0; nt < 4; nt++) {                               \
                    asm volatile(                                              \
                        "mma.sync.aligned.m16n8k8.row.col.f32.tf32.tf32.f32 "  \
                        "{%0,%1,%2,%3}, {%4,%5,%6,%7}, {%8,%9}, {%0,%1,%2,%3};\n" \
                        : "+f"(acc[mt][nt][0]), "+f"(acc[mt][nt][1]),          \
                          "+f"(acc[mt][nt][2]), "+f"(acc[mt][nt][3])           \
                        : "r"(af[mt][0]), "r"(af[mt][1]),                      \
                          "r"(af[mt][2]), "r"(af[mt][3]),                      \
                          "r"(bf[nt][0]), "r"(bf[nt][1]));                     \
                }                                                              \
        }                                                                      \
        st  = (st  == NSTAGE-1) ? 0 : st  + 1;                                 \
        st2 = (st2 == NSTAGE-1) ? 0 : st2 + 1;                                 \
    }

// ---------------------------------------------------------------------------
// Plain GEMM (conv + MLP layers 1,2): bias (+relu) (+tf32-round), store C.
// flags: bit0 = relu, bit1 = round output to tf32.
// ---------------------------------------------------------------------------
__global__ __launch_bounds__(256, 2)
void k_mma_tf32(const float* __restrict__ A, const float* __restrict__ B,
                const float* __restrict__ bias, float* __restrict__ C,
                int M, int N, int K, int flags)
{
    extern __shared__ float dynsmem[];
    float* Asm = dynsmem;
    float* Bsm = dynsmem + NSTAGE*SMBUF;

    const int tid  = threadIdx.x;
    const int warp = tid >> 5;
    const int lane = tid & 31;
    const int wm   = warp & 1;
    const int wn   = warp >> 1;
    const int m0 = blockIdx.y * 128;
    const int n0 = blockIdx.x * 128;

    float acc[4][4][4];
#pragma unroll
    for (int mt = 0; mt < 4; mt++)
#pragma unroll
        for (int nt = 0; nt < 4; nt++)
#pragma unroll
            for (int r = 0; r < 4; r++) acc[mt][nt][r] = 0.f;

    GEMM_MAINLOOP(K)

    const bool do_relu  = (flags & 1) != 0;
    const bool do_round = (flags & 2) != 0;
#pragma unroll
    for (int mt = 0; mt < 4; mt++) {
        const int rrow = m0 + wm*64 + mt*16 + (lane >> 2);
#pragma unroll
        for (int nt = 0; nt < 4; nt++) {
            const int col = n0 + wn*32 + nt*8 + 2*(lane & 3);
            const float bz0 = bias[col];
            const float bz1 = bias[col + 1];
            float v0 = acc[mt][nt][0] + bz0;
            float v1 = acc[mt][nt][1] + bz1;
            float v2 = acc[mt][nt][2] + bz0;
            float v3 = acc[mt][nt][3] + bz1;
            if (do_relu) {
                v0 = fmaxf(v0, 0.f); v1 = fmaxf(v1, 0.f);
                v2 = fmaxf(v2, 0.f); v3 = fmaxf(v3, 0.f);
            }
            if (do_round) {
                v0 = roundtf(v0); v1 = roundtf(v1);
                v2 = roundtf(v2); v3 = roundtf(v3);
            }
            *(float2*)(C + (size_t)rrow * N + col)       = make_float2(v0, v1);
            *(float2*)(C + (size_t)(rrow + 8) * N + col) = make_float2(v2, v3);
        }
    }
}

// ---------------------------------------------------------------------------
// Layer-3 GEMM fused with W4: pred_half[c] = dot(relu(acc+bias), w4[c]) over
// this CTA's 128 columns; written to g_pred[blockIdx.x] (one writer per slot).
// grid = (2, NROWS/128); blockIdx.x selects the n-half.
// ---------------------------------------------------------------------------
__global__ __launch_bounds__(256, 2)
void k_mma_w4(const float* __restrict__ A, const float* __restrict__ B,
              const float* __restrict__ bias, const float* __restrict__ w4,
              float* __restrict__ pred_out, int K)
{
    extern __shared__ float dynsmem[];
    float* Asm    = dynsmem;
    float* Bsm    = dynsmem + NSTAGE*SMBUF;
    float* s_pred = dynsmem + 2*NSTAGE*SMBUF;   // [128][4]

    const int tid  = threadIdx.x;
    const int warp = tid >> 5;
    const int lane = tid & 31;
    const int wm   = warp & 1;
    const int wn   = warp >> 1;
    const int m0 = blockIdx.y * 128;
    const int n0 = blockIdx.x * 128;

    for (int i = tid; i < 512; i += 256) s_pred[i] = 0.f;

    float acc[4][4][4];
#pragma unroll
    for (int mt = 0; mt < 4; mt++)
#pragma unroll
        for (int nt = 0; nt < 4; nt++)
#pragma unroll
            for (int r = 0; r < 4; r++) acc[mt][nt][r] = 0.f;

    GEMM_MAINLOOP(K)

#pragma unroll
    for (int mt = 0; mt < 4; mt++) {
        float p0[3] = {0.f, 0.f, 0.f};   // row r
        float p1[3] = {0.f, 0.f, 0.f};   // row r+8
#pragma unroll
        for (int nt = 0; nt < 4; nt++) {
#pragma unroll
            for (int e = 0; e < 2; e++) {
                const int col = n0 + wn*32 + nt*8 + 2*(lane & 3) + e;
                const float bz = bias[col];
                const float w40 = w4[col];
                const float w41 = w4[HD + col];
                const float w42 = w4[2*HD + col];
                float v0 = fmaxf(acc[mt][nt][e]     + bz, 0.f);
                float v1 = fmaxf(acc[mt][nt][2 + e] + bz, 0.f);
                p0[0] += v0*w40; p0[1] += v0*w41; p0[2] += v0*w42;
                p1[0] += v1*w40; p1[1] += v1*w41; p1[2] += v1*w42;
            }
        }
#pragma unroll
        for (int c = 0; c < 3; c++) {
            p0[c] += __shfl_xor_sync(0xffffffffu, p0[c], 1);
            p0[c] += __shfl_xor_sync(0xffffffffu, p0[c], 2);
            p1[c] += __shfl_xor_sync(0xffffffffu, p1[c], 1);
            p1[c] += __shfl_xor_sync(0xffffffffu, p1[c], 2);
        }
        if ((lane & 3) == 0) {
            const int lr0 = wm*64 + mt*16 + (lane >> 2);
#pragma unroll
            for (int c = 0; c < 3; c++) {
                atomicAdd(&s_pred[lr0*4 + c],       p0[c]);   // smem, 4 writers
                atomicAdd(&s_pred[(lr0 + 8)*4 + c], p1[c]);
            }
        }
    }
    __syncthreads();
    if (tid < 128) {
        float* gp = pred_out + (size_t)blockIdx.x * ((size_t)NROWS * 3)
                  + (size_t)(m0 + tid) * 3;
        gp[0] = s_pred[tid*4 + 0];
        gp[1] = s_pred[tid*4 + 1];
        gp[2] = s_pred[tid*4 + 2];
    }
}

// ---------------------------------------------------------------------------
// Assemble: one block per query q; builds all 8 rows (img, s) of g_x plus
// area. t = tid&127 selects the freq pair; tid>>7 selects cos/sin half.
// ---------------------------------------------------------------------------
__global__ __launch_bounds__(256)
void k_assemble(const float* __restrict__ coord, const float* __restrict__ cell,
                const float* __restrict__ phase_w)
{
    const int q  = blockIdx.x;
    const int t  = threadIdx.x & 127;
    const int hf = threadIdx.x >> 7;      // 0 = cos half, 1 = sin half

    const float cy = coord[2*q + 0];
    const float cx = coord[2*q + 1];
    const float rc0 = cell[2*q + 0] * 128.f;
    const float rc1 = cell[2*q + 1] * 128.f;
    const float ph  = rc0 * phase_w[2*t + 0] + rc1 * phase_w[2*t + 1];

    const float RX  = 1.f / 128.f;
    const float EPS = 1e-6f;
    const float LO  = -1.0f + 1e-6f;
    const float HI  =  1.0f - 1e-6f;

#pragma unroll
    for (int s = 0; s < 4; s++) {
        const float vx = (s & 2) ? 1.f : -1.f;
        const float vy = (s & 1) ? 1.f : -1.f;

        float cys = fminf(fmaxf(cy + (vx*RX + EPS), LO), HI);
        float cxs = fminf(fmaxf(cx + (vy*RX + EPS), LO), HI);

        int iy = (int)rintf(((cys + 1.f)*128.f - 1.f)*0.5f);
        int ix = (int)rintf(((cxs + 1.f)*128.f - 1.f)*0.5f);
        iy = min(max(iy, 0), 127);
        ix = min(max(ix, 0), 127);

        const float qcy = -1.f + (1.f/128.f) + (2.f/128.f)*(float)iy;
        const float qcx = -1.f + (1.f/128.f) + (2.f/128.f)*(float)ix;
        const float rel0 = (cy - qcy) * 128.f;
        const float rel1 = (cx - qcx) * 128.f;

        if (threadIdx.x == 0) {
            const float ar = fabsf(rel0 * rel1) + 1e-9f;
            g_area[((size_t)s       << 16) + q] = ar;   // img 0
            g_area[((size_t)(4 + s) << 16) + q] = ar;   // img 1 (identical)
        }

        const int pix = iy * WF + ix;
#pragma unroll
        for (int img = 0; img < 2; img++) {
            const float* cp = g_cf + ((size_t)img * NPIX + pix) * NCF;
            const float f0 = cp[HD + 2*t];
            const float f1 = cp[HD + 2*t + 1];
            const float qf = f0 * rel0 + f1 * rel1 + ph;
            float sv, cv;
            __sincosf(3.14159265358979f * qf, &sv, &cv);
            const float trig = hf ? sv : cv;
            const size_t r = ((size_t)((img << 2) + s) << 16) + q;
            g_x[r * HD + hf*128 + t] = roundtf(cp[hf*128 + t] * trig);
        }
    }
}

// ---------------------------------------------------------------------------
// Finalize (light): sum the two pred halves, blend (order [3,2,1,0]) + b4,
// bilinear-border of inp, write NCHW output. One thread per (img, q).
// ---------------------------------------------------------------------------
__global__ __launch_bounds__(256)
void k_finalize(const float* __restrict__ inp, const float* __restrict__ coord,
                const float* __restrict__ b4, float* __restrict__ out)
{
    const int gq = blockIdx.x * 256 + threadIdx.x;     // 0 .. 131071
    const int img = gq >> 16;
    const int q   = gq & (NQ - 1);

    float pred[4][3];
    float area[4];
#pragma unroll
    for (int s = 0; s < 4; s++) {
        const size_t rowi = ((size_t)(img*4 + s) << 16) + q;
        const float* gp0 = g_pred[0] + rowi * 3;
        const float* gp1 = g_pred[1] + rowi * 3;
        pred[s][0] = gp0[0] + gp1[0];
        pred[s][1] = gp0[1] + gp1[1];
        pred[s][2] = gp0[2] + gp1[2];
        area[s] = g_area[rowi];
    }

    const float tot = area[0] + area[1] + area[2] + area[3];
    const float w0 = area[3] / tot;   // order = [3,2,1,0]
    const float w1 = area[2] / tot;
    const float w2 = area[1] / tot;
    const float w3 = area[0] / tot;

    // bilinear (border clamp) on inp at coord
    const float cy = coord[2*q + 0];
    const float cx = coord[2*q + 1];
    float y = fminf(fmaxf(((cy + 1.f)*128.f - 1.f)*0.5f, 0.f), 127.f);
    float x = fminf(fmaxf(((cx + 1.f)*128.f - 1.f)*0.5f, 0.f), 127.f);
    float y0f = floorf(y), x0f = floorf(x);
    int y0 = (int)y0f, x0 = (int)x0f;
    float wy = y - y0f, wx = x - x0f;
    int y1 = min(y0 + 1, 127), x1 = min(x0 + 1, 127);

#pragma unroll
    for (int c = 0; c < 3; c++) {
        float ret = pred[0][c]*w0 + pred[1][c]*w1 + pred[2][c]*w2 + pred[3][c]*w3
                  + b4[c];
        const float* ip = inp + ((size_t)img*3 + c) * NPIX;
        float v00 = ip[y0*WF + x0];
        float v01 = ip[y0*WF + x1];
        float v10 = ip[y1*WF + x0];
        float v11 = ip[y1*WF + x1];
        float bv = v00*(1.f-wy)*(1.f-wx) + v01*(1.f-wy)*wx
                 + v10*wy*(1.f-wx)       + v11*wy*wx;
        out[(((size_t)img*3 + c) << 16) + q] = ret + bv;
    }
}

// ---------------------------------------------------------------------------
// Launch
// ---------------------------------------------------------------------------
extern "C" void kernel_launch(void* const* d_in, const int* in_sizes, int n_in,
                              void* d_out, int out_size)
{
    const float* feat    = (const float*)d_in[0];
    const float* inp     = (const float*)d_in[1];
    const float* coord   = (const float*)d_in[2];
    const float* cell    = (const float*)d_in[3];
    const float* coef_w  = (const float*)d_in[4];
    const float* coef_b  = (const float*)d_in[5];
    const float* freq_w  = (const float*)d_in[6];
    const float* freq_b  = (const float*)d_in[7];
    const float* phase_w = (const float*)d_in[8];
    const float* w1 = (const float*)d_in[9],  *b1 = (const float*)d_in[10];
    const float* w2 = (const float*)d_in[11], *b2 = (const float*)d_in[12];
    const float* w3 = (const float*)d_in[13], *b3 = (const float*)d_in[14];
    const float* w4 = (const float*)d_in[15], *b4 = (const float*)d_in[16];
    float* out = (float*)d_out;

    void *p_col, *p_cf, *p_x, *p_h, *p_wr, *p_pred, *p_cfb;
    cudaGetSymbolAddress(&p_col,  g_col);
    cudaGetSymbolAddress(&p_cf,   g_cf);
    cudaGetSymbolAddress(&p_x,    g_x);
    cudaGetSymbolAddress(&p_h,    g_h);
    cudaGetSymbolAddress(&p_wr,   g_wr);
    cudaGetSymbolAddress(&p_pred, g_pred);
    cudaGetSymbolAddress(&p_cfb,  g_cfb);
    float* col_f  = (float*)p_col;
    float* cf_f   = (float*)p_cf;
    float* x_f    = (float*)p_x;
    float* h_f    = (float*)p_h;
    float* wr_f   = (float*)p_wr;
    float* pred_f = (float*)p_pred;
    float* cfb_f  = (float*)p_cfb;
    (void)cfb_f;

    cudaFuncSetAttribute(k_mma_tf32,
                         cudaFuncAttributeMaxDynamicSharedMemorySize,
                         SMEM_GEMM_BYTES);
    cudaFuncSetAttribute(k_mma_w4,
                         cudaFuncAttributeMaxDynamicSharedMemorySize,
                         SMEM_W4_BYTES);

    // launch #1: all weight prep in one kernel
    k_prep<<<(PREP_TOTAL + 255)/256, 256>>>(w1, w2, w3, coef_w, freq_w,
                                            coef_b, freq_b);

    // launch #2: im2col (both images), tf32-rounded
    {
        const size_t total = (size_t)NIMG * NPIX * KCOL;
        k_im2col<<<(unsigned)((total + 255) / 256), 256>>>(feat);
    }

    // launches #3,#4: merged conv-as-GEMM: coef|freq (N=512), NHWC fp32
    for (int img = 0; img < NIMG; img++) {
        const float* A = col_f + (size_t)img * NPIX * KCOL;
        k_mma_tf32<<<dim3(NCF/128, NPIX/128), 256, SMEM_GEMM_BYTES>>>(
            A, wr_f + WR_CFW, cfb_f, cf_f + (size_t)img * NPIX * NCF,
            NPIX, NCF, KCOL, 0);
    }

    // launch #5: per-query assemble -> g_x rows (tf32-rounded)
    k_assemble<<<NQ, 256>>>(coord, cell, phase_w);

    // launch #6 (ncu capture slot): MLP layer 1; then 2; then fused layer 3
    k_mma_tf32<<<dim3(HD/128, NROWS/128), 256, SMEM_GEMM_BYTES>>>(
        x_f, wr_f + WR_W1, b1, h_f, NROWS, HD, HD, 3);
    k_mma_tf32<<<dim3(HD/128, NROWS/128), 256, SMEM_GEMM_BYTES>>>(
        h_f, wr_f + WR_W2, b2, x_f, NROWS, HD, HD, 3);
    k_mma_w4<<<dim3(2, NROWS/128), 256, SMEM_W4_BYTES>>>(
        x_f, wr_f + WR_W3, b3, w4, pred_f, HD);

    // blend + bilinear + write out (light)
    k_finalize<<<(NIMG*NQ)/256, 256>>>(inp, coord, b4, out);
}

// round 14
// speedup vs baseline: 1.1582x; 1.1582x over previous
#include <cuda_runtime.h>
#include <cuda_bf16.h>
#include <cstdint>
#include <cstddef>

// ---------------------------------------------------------------------------
// Problem constants
// ---------------------------------------------------------------------------
#define NIMG   2
#define CIN    64
#define HF     128
#define WF     128
#define NPIX   (HF*WF)        // 16384
#define HD     256
#define KCOL   (CIN*9)        // 576
#define HO     256
#define WO     256
#define NQ     (HO*WO)        // 65536
#define NROWS  (NIMG*4*NQ)    // 524288
#define NCF    512            // merged coef|freq channel count

// ---------------------------------------------------------------------------
// Scratch (device globals; allocation-free)
// ---------------------------------------------------------------------------
__device__ float g_col [(size_t)NIMG*NPIX*KCOL];   // im2col (tf32-rounded)
__device__ float g_cf  [(size_t)NIMG*NPIX*NCF];    // NHWC coef|freq (fp32) 64MB
__device__ float g_x   [(size_t)NROWS*HD];         // activations
__device__ float g_h   [(size_t)NROWS*HD];         // activations
__device__ float g_area[(size_t)NROWS];
__device__ float g_pred[2][(size_t)NROWS*3];       // per-n-half partial preds
__device__ float g_wr  [3*HD*HD + 2*HD*KCOL];      // tf32-rounded weights
__device__ float g_cfb [NCF];                      // concat conv bias (raw)

#define WR_W1    0
#define WR_W2    (HD*HD)
#define WR_W3    (2*HD*HD)
#define WR_CFW   (3*HD*HD)            // [512][576]: rows 0-255 coef, 256-511 freq

__device__ __forceinline__ uint32_t f2tf32(float f)
{
    uint32_t r;
    asm("cvt.rna.tf32.f32 %0, %1;" : "=r"(r) : "f"(f));
    return r;
}
__device__ __forceinline__ float roundtf(float f)
{
    return __uint_as_float(f2tf32(f));
}
__device__ __forceinline__ void cp16(uint32_t dst, const void* src)
{
    asm volatile("cp.async.ca.shared.global [%0], [%1], 16;" :: "r"(dst), "l"(src));
}

// ---------------------------------------------------------------------------
// k_prep: single launch that tf32-rounds all 5 weight matrices and builds the
// concatenated conv bias.
// ---------------------------------------------------------------------------
#define PREP_TOTAL (3*HD*HD + 2*HD*KCOL + NCF)
__global__ void k_prep(const float* __restrict__ w1, const float* __restrict__ w2,
                       const float* __restrict__ w3, const float* __restrict__ cw,
                       const float* __restrict__ fw, const float* __restrict__ cb,
                       const float* __restrict__ fb)
{
    int i = blockIdx.x * blockDim.x + threadIdx.x;
    if (i >= PREP_TOTAL) return;
    if (i < 3*HD*HD + 2*HD*KCOL) {
        const float* src;
        int j = i;
        if (j < HD*HD)            { src = w1; }
        else if (j < 2*HD*HD)     { src = w2; j -= HD*HD; }
        else if (j < 3*HD*HD)     { src = w3; j -= 2*HD*HD; }
        else if (j < 3*HD*HD + HD*KCOL) { src = cw; j -= 3*HD*HD; }
        else                      { src = fw; j -= 3*HD*HD + HD*KCOL; }
        g_wr[i] = roundtf(src[j]);
    } else {
        int j = i - (3*HD*HD + 2*HD*KCOL);
        g_cfb[j] = (j < HD) ? cb[j] : fb[j - HD];
    }
}

// ---------------------------------------------------------------------------
// im2col: g_col[img][pix][ic*9 + ky*3 + kx], zero-padded 3x3, tf32-rounded
// ---------------------------------------------------------------------------
__global__ void k_im2col(const float* __restrict__ feat)
{
    size_t idx = (size_t)blockIdx.x * blockDim.x + threadIdx.x;
    const size_t total = (size_t)NIMG * NPIX * KCOL;
    if (idx >= total) return;
    int col = (int)(idx % KCOL);
    size_t pi = idx / KCOL;
    int pix = (int)(pi % NPIX);
    int img = (int)(pi / NPIX);
    int ic = col / 9;
    int k  = col % 9;
    int ky = k / 3, kx = k % 3;
    int y = pix / WF, x = pix % WF;
    int gy = y + ky - 1, gx = x + kx - 1;
    float v = 0.f;
    if ((unsigned)gy < (unsigned)HF && (unsigned)gx < (unsigned)WF)
        v = feat[(((size_t)img*CIN + ic)*HF + gy)*WF + gx];
    g_col[idx] = roundtf(v);
}

// ---------------------------------------------------------------------------
// GEMM config (R12-proven, REVERTED from 3-stage): BM=BN=128, BK=32,
// 256 threads, 8 warps (2x4), warp tile 64x32, mma m16n8k8,
// 2-stage cp.async double buffer.
// ---------------------------------------------------------------------------
#define BK     32
#define SMROW  36                      // 32 data + 4 pad; banks (4r+c)%32 unique
#define SMBUF  (128*SMROW)             // floats per buffer per matrix
#define SMEM_GEMM_BYTES (4 * SMBUF * 4)          // 73728 B (plain kernel)
#define SMEM_W4_BYTES   (4 * SMBUF * 4 + 2048)   // + s_pred[128][4]

// Mainloop macro. Produces acc[4][4][4]; uses names: A, B, m0, n0, tid,
// Asm, Bsm, wm, wn, lane.
#define GEMM_MAINLOOP(Kval)                                                    \
    const int row  = tid >> 1;                                                 \
    const int half = tid & 1;                                                  \
    const float* Ap = A + (size_t)(m0 + row) * (Kval) + half*16;               \
    const float* Bp = B + (size_t)(n0 + row) * (Kval) + half*16;               \
    const uint32_t sA0 = (uint32_t)__cvta_generic_to_shared(Asm)               \
                       + (row*SMROW + half*16)*4;                              \
    const uint32_t sB0 = (uint32_t)__cvta_generic_to_shared(Bsm)               \
                       + (row*SMROW + half*16)*4;                              \
    const uint32_t bufb = SMBUF * 4;                                           \
    const int abase = (wm*64 + (lane>>2)) * SMROW + (lane & 3);                \
    const int bbase = (wn*32 + (lane>>2)) * SMROW + (lane & 3);                \
    _Pragma("unroll")                                                          \
    for (int i = 0; i < 4; i++) cp16(sA0 + i*16, Ap + i*4);                    \
    _Pragma("unroll")                                                          \
    for (int i = 0; i < 4; i++) cp16(sB0 + i*16, Bp + i*4);                    \
    asm volatile("cp.async.commit_group;" ::: "memory");                       \
    const int nslab = (Kval) / BK;                                             \
    int buf = 0;                                                               \
    for (int s = 0; s < nslab; s++) {                                          \
        if (s + 1 < nslab) {                                                   \
            const int ko = (s + 1) * BK;                                       \
            const uint32_t bo = (uint32_t)(buf ^ 1) * bufb;                    \
            _Pragma("unroll")                                                  \
            for (int i = 0; i < 4; i++) cp16(sA0 + bo + i*16, Ap + ko + i*4);  \
            _Pragma("unroll")                                                  \
            for (int i = 0; i < 4; i++) cp16(sB0 + bo + i*16, Bp + ko + i*4);  \
            asm volatile("cp.async.commit_group;" ::: "memory");               \
            asm volatile("cp.async.wait_group 1;" ::: "memory");               \
        } else {                                                               \
            asm volatile("cp.async.wait_group 0;" ::: "memory");               \
        }                                                                      \
        __syncthreads();                                                       \
        const uint32_t* as = (const uint32_t*)(Asm + buf*SMBUF);               \
        const uint32_t* bs = (const uint32_t*)(Bsm + buf*SMBUF);               \
        _Pragma("unroll")                                                      \
        for (int ks = 0; ks < 4; ks++) {                                       \
            uint32_t af[4][4], bf[4][2];                                       \
            _Pragma("unroll")                                                  \
            for (int mt = 0; mt < 4; mt++) {                                   \
                const int o = abase + mt*(16*SMROW) + ks*8;                    \
                af[mt][0] = as[o];                                             \
                af[mt][1] = as[o + 8*SMROW];                                   \
                af[mt][2] = as[o + 4];                                         \
                af[mt][3] = as[o + 8*SMROW + 4];                               \
            }                                                                  \
            _Pragma("unroll")                                                  \
            for (int nt = 0; nt < 4; nt++) {                                   \
                const int o = bbase + nt*(8*SMROW) + ks*8;                     \
                bf[nt][0] = bs[o];                                             \
                bf[nt][1] = bs[o + 4];                                         \
            }                                                                  \
            _Pragma("unroll")                                                  \
            for (int mt = 0; mt < 4; mt++)                                     \
                _Pragma("unroll")                                              \
                for (int nt = 0; nt < 4; nt++) {                               \
                    asm volatile(                                              \
                        "mma.sync.aligned.m16n8k8.row.col.f32.tf32.tf32.f32 "  \
                        "{%0,%1,%2,%3}, {%4,%5,%6,%7}, {%8,%9}, {%0,%1,%2,%3};\n" \
                        : "+f"(acc[mt][nt][0]), "+f"(acc[mt][nt][1]),          \
                          "+f"(acc[mt][nt][2]), "+f"(acc[mt][nt][3])           \
                        : "r"(af[mt][0]), "r"(af[mt][1]),                      \
                          "r"(af[mt][2]), "r"(af[mt][3]),                      \
                          "r"(bf[nt][0]), "r"(bf[nt][1]));                     \
                }                                                              \
        }                                                                      \
        __syncthreads();                                                       \
        buf ^= 1;                                                              \
    }

// ---------------------------------------------------------------------------
// Plain GEMM (conv + MLP layers 1,2): bias (+relu) (+tf32-round), store C.
// flags: bit0 = relu, bit1 = round output to tf32.
// ---------------------------------------------------------------------------
__global__ __launch_bounds__(256, 2)
void k_mma_tf32(const float* __restrict__ A, const float* __restrict__ B,
                const float* __restrict__ bias, float* __restrict__ C,
                int M, int N, int K, int flags)
{
    extern __shared__ float dynsmem[];
    float* Asm = dynsmem;
    float* Bsm = dynsmem + 2*SMBUF;

    const int tid  = threadIdx.x;
    const int warp = tid >> 5;
    const int lane = tid & 31;
    const int wm   = warp & 1;
    const int wn   = warp >> 1;
    const int m0 = blockIdx.y * 128;
    const int n0 = blockIdx.x * 128;

    float acc[4][4][4];
#pragma unroll
    for (int mt = 0; mt < 4; mt++)
#pragma unroll
        for (int nt = 0; nt < 4; nt++)
#pragma unroll
            for (int r = 0; r < 4; r++) acc[mt][nt][r] = 0.f;

    GEMM_MAINLOOP(K)

    const bool do_relu  = (flags & 1) != 0;
    const bool do_round = (flags & 2) != 0;
#pragma unroll
    for (int mt = 0; mt < 4; mt++) {
        const int rrow = m0 + wm*64 + mt*16 + (lane >> 2);
#pragma unroll
        for (int nt = 0; nt < 4; nt++) {
            const int col = n0 + wn*32 + nt*8 + 2*(lane & 3);
            const float bz0 = bias[col];
            const float bz1 = bias[col + 1];
            float v0 = acc[mt][nt][0] + bz0;
            float v1 = acc[mt][nt][1] + bz1;
            float v2 = acc[mt][nt][2] + bz0;
            float v3 = acc[mt][nt][3] + bz1;
            if (do_relu) {
                v0 = fmaxf(v0, 0.f); v1 = fmaxf(v1, 0.f);
                v2 = fmaxf(v2, 0.f); v3 = fmaxf(v3, 0.f);
            }
            if (do_round) {
                v0 = roundtf(v0); v1 = roundtf(v1);
                v2 = roundtf(v2); v3 = roundtf(v3);
            }
            *(float2*)(C + (size_t)rrow * N + col)       = make_float2(v0, v1);
            *(float2*)(C + (size_t)(rrow + 8) * N + col) = make_float2(v2, v3);
        }
    }
}

// ---------------------------------------------------------------------------
// Layer-3 GEMM fused with W4: pred_half[c] = dot(relu(acc+bias), w4[c]) over
// this CTA's 128 columns; written to g_pred[blockIdx.x] (one writer per slot).
// grid = (2, NROWS/128); blockIdx.x selects the n-half.
// ---------------------------------------------------------------------------
__global__ __launch_bounds__(256, 2)
void k_mma_w4(const float* __restrict__ A, const float* __restrict__ B,
              const float* __restrict__ bias, const float* __restrict__ w4,
              float* __restrict__ pred_out, int K)
{
    extern __shared__ float dynsmem[];
    float* Asm    = dynsmem;
    float* Bsm    = dynsmem + 2*SMBUF;
    float* s_pred = dynsmem + 4*SMBUF;   // [128][4]

    const int tid  = threadIdx.x;
    const int warp = tid >> 5;
    const int lane = tid & 31;
    const int wm   = warp & 1;
    const int wn   = warp >> 1;
    const int m0 = blockIdx.y * 128;
    const int n0 = blockIdx.x * 128;

    for (int i = tid; i < 512; i += 256) s_pred[i] = 0.f;

    float acc[4][4][4];
#pragma unroll
    for (int mt = 0; mt < 4; mt++)
#pragma unroll
        for (int nt = 0; nt < 4; nt++)
#pragma unroll
            for (int r = 0; r < 4; r++) acc[mt][nt][r] = 0.f;

    GEMM_MAINLOOP(K)

#pragma unroll
    for (int mt = 0; mt < 4; mt++) {
        float p0[3] = {0.f, 0.f, 0.f};   // row r
        float p1[3] = {0.f, 0.f, 0.f};   // row r+8
#pragma unroll
        for (int nt = 0; nt < 4; nt++) {
#pragma unroll
            for (int e = 0; e < 2; e++) {
                const int col = n0 + wn*32 + nt*8 + 2*(lane & 3) + e;
                const float bz = bias[col];
                const float w40 = w4[col];
                const float w41 = w4[HD + col];
                const float w42 = w4[2*HD + col];
                float v0 = fmaxf(acc[mt][nt][e]     + bz, 0.f);
                float v1 = fmaxf(acc[mt][nt][2 + e] + bz, 0.f);
                p0[0] += v0*w40; p0[1] += v0*w41; p0[2] += v0*w42;
                p1[0] += v1*w40; p1[1] += v1*w41; p1[2] += v1*w42;
            }
        }
#pragma unroll
        for (int c = 0; c < 3; c++) {
            p0[c] += __shfl_xor_sync(0xffffffffu, p0[c], 1);
            p0[c] += __shfl_xor_sync(0xffffffffu, p0[c], 2);
            p1[c] += __shfl_xor_sync(0xffffffffu, p1[c], 1);
            p1[c] += __shfl_xor_sync(0xffffffffu, p1[c], 2);
        }
        if ((lane & 3) == 0) {
            const int lr0 = wm*64 + mt*16 + (lane >> 2);
#pragma unroll
            for (int c = 0; c < 3; c++) {
                atomicAdd(&s_pred[lr0*4 + c],       p0[c]);   // smem, 4 writers
                atomicAdd(&s_pred[(lr0 + 8)*4 + c], p1[c]);
            }
        }
    }
    __syncthreads();
    if (tid < 128) {
        float* gp = pred_out + (size_t)blockIdx.x * ((size_t)NROWS * 3)
                  + (size_t)(m0 + tid) * 3;
        gp[0] = s_pred[tid*4 + 0];
        gp[1] = s_pred[tid*4 + 1];
        gp[2] = s_pred[tid*4 + 2];
    }
}

// ---------------------------------------------------------------------------
// Assemble: one block per query q; builds all 8 rows (img, s) of g_x plus
// area. t = tid&127 selects the freq pair; tid>>7 selects cos/sin half.
// ---------------------------------------------------------------------------
__global__ __launch_bounds__(256)
void k_assemble(const float* __restrict__ coord, const float* __restrict__ cell,
                const float* __restrict__ phase_w)
{
    const int q  = blockIdx.x;
    const int t  = threadIdx.x & 127;
    const int hf = threadIdx.x >> 7;      // 0 = cos half, 1 = sin half

    const float cy = coord[2*q + 0];
    const float cx = coord[2*q + 1];
    const float rc0 = cell[2*q + 0] * 128.f;
    const float rc1 = cell[2*q + 1] * 128.f;
    const float ph  = rc0 * phase_w[2*t + 0] + rc1 * phase_w[2*t + 1];

    const float RX  = 1.f / 128.f;
    const float EPS = 1e-6f;
    const float LO  = -1.0f + 1e-6f;
    const float HI  =  1.0f - 1e-6f;

#pragma unroll
    for (int s = 0; s < 4; s++) {
        const float vx = (s & 2) ? 1.f : -1.f;
        const float vy = (s & 1) ? 1.f : -1.f;

        float cys = fminf(fmaxf(cy + (vx*RX + EPS), LO), HI);
        float cxs = fminf(fmaxf(cx + (vy*RX + EPS), LO), HI);

        int iy = (int)rintf(((cys + 1.f)*128.f - 1.f)*0.5f);
        int ix = (int)rintf(((cxs + 1.f)*128.f - 1.f)*0.5f);
        iy = min(max(iy, 0), 127);
        ix = min(max(ix, 0), 127);

        const float qcy = -1.f + (1.f/128.f) + (2.f/128.f)*(float)iy;
        const float qcx = -1.f + (1.f/128.f) + (2.f/128.f)*(float)ix;
        const float rel0 = (cy - qcy) * 128.f;
        const float rel1 = (cx - qcx) * 128.f;

        if (threadIdx.x == 0) {
            const float ar = fabsf(rel0 * rel1) + 1e-9f;
            g_area[((size_t)s       << 16) + q] = ar;   // img 0
            g_area[((size_t)(4 + s) << 16) + q] = ar;   // img 1 (identical)
        }

        const int pix = iy * WF + ix;
#pragma unroll
        for (int img = 0; img < 2; img++) {
            const float* cp = g_cf + ((size_t)img * NPIX + pix) * NCF;
            const float f0 = cp[HD + 2*t];
            const float f1 = cp[HD + 2*t + 1];
            const float qf = f0 * rel0 + f1 * rel1 + ph;
            float sv, cv;
            __sincosf(3.14159265358979f * qf, &sv, &cv);
            const float trig = hf ? sv : cv;
            const size_t r = ((size_t)((img << 2) + s) << 16) + q;
            g_x[r * HD + hf*128 + t] = roundtf(cp[hf*128 + t] * trig);
        }
    }
}

// ---------------------------------------------------------------------------
// Finalize (light): sum the two pred halves, blend (order [3,2,1,0]) + b4,
// bilinear-border of inp, write NCHW output. One thread per (img, q).
// ---------------------------------------------------------------------------
__global__ __launch_bounds__(256)
void k_finalize(const float* __restrict__ inp, const float* __restrict__ coord,
                const float* __restrict__ b4, float* __restrict__ out)
{
    const int gq = blockIdx.x * 256 + threadIdx.x;     // 0 .. 131071
    const int img = gq >> 16;
    const int q   = gq & (NQ - 1);

    float pred[4][3];
    float area[4];
#pragma unroll
    for (int s = 0; s < 4; s++) {
        const size_t rowi = ((size_t)(img*4 + s) << 16) + q;
        const float* gp0 = g_pred[0] + rowi * 3;
        const float* gp1 = g_pred[1] + rowi * 3;
        pred[s][0] = gp0[0] + gp1[0];
        pred[s][1] = gp0[1] + gp1[1];
        pred[s][2] = gp0[2] + gp1[2];
        area[s] = g_area[rowi];
    }

    const float tot = area[0] + area[1] + area[2] + area[3];
    const float w0 = area[3] / tot;   // order = [3,2,1,0]
    const float w1 = area[2] / tot;
    const float w2 = area[1] / tot;
    const float w3 = area[0] / tot;

    // bilinear (border clamp) on inp at coord
    const float cy = coord[2*q + 0];
    const float cx = coord[2*q + 1];
    float y = fminf(fmaxf(((cy + 1.f)*128.f - 1.f)*0.5f, 0.f), 127.f);
    float x = fminf(fmaxf(((cx + 1.f)*128.f - 1.f)*0.5f, 0.f), 127.f);
    float y0f = floorf(y), x0f = floorf(x);
    int y0 = (int)y0f, x0 = (int)x0f;
    float wy = y - y0f, wx = x - x0f;
    int y1 = min(y0 + 1, 127), x1 = min(x0 + 1, 127);

#pragma unroll
    for (int c = 0; c < 3; c++) {
        float ret = pred[0][c]*w0 + pred[1][c]*w1 + pred[2][c]*w2 + pred[3][c]*w3
                  + b4[c];
        const float* ip = inp + ((size_t)img*3 + c) * NPIX;
        float v00 = ip[y0*WF + x0];
        float v01 = ip[y0*WF + x1];
        float v10 = ip[y1*WF + x0];
        float v11 = ip[y1*WF + x1];
        float bv = v00*(1.f-wy)*(1.f-wx) + v01*(1.f-wy)*wx
                 + v10*wy*(1.f-wx)       + v11*wy*wx;
        out[(((size_t)img*3 + c) << 16) + q] = ret + bv;
    }
}

// ---------------------------------------------------------------------------
// Launch
// ---------------------------------------------------------------------------
extern "C" void kernel_launch(void* const* d_in, const int* in_sizes, int n_in,
                              void* d_out, int out_size)
{
    const float* feat    = (const float*)d_in[0];
    const float* inp     = (const float*)d_in[1];
    const float* coord   = (const float*)d_in[2];
    const float* cell    = (const float*)d_in[3];
    const float* coef_w  = (const float*)d_in[4];
    const float* coef_b  = (const float*)d_in[5];
    const float* freq_w  = (const float*)d_in[6];
    const float* freq_b  = (const float*)d_in[7];
    const float* phase_w = (const float*)d_in[8];
    const float* w1 = (const float*)d_in[9],  *b1 = (const float*)d_in[10];
    const float* w2 = (const float*)d_in[11], *b2 = (const float*)d_in[12];
    const float* w3 = (const float*)d_in[13], *b3 = (const float*)d_in[14];
    const float* w4 = (const float*)d_in[15], *b4 = (const float*)d_in[16];
    float* out = (float*)d_out;

    void *p_col, *p_cf, *p_x, *p_h, *p_wr, *p_pred, *p_cfb;
    cudaGetSymbolAddress(&p_col,  g_col);
    cudaGetSymbolAddress(&p_cf,   g_cf);
    cudaGetSymbolAddress(&p_x,    g_x);
    cudaGetSymbolAddress(&p_h,    g_h);
    cudaGetSymbolAddress(&p_wr,   g_wr);
    cudaGetSymbolAddress(&p_pred, g_pred);
    cudaGetSymbolAddress(&p_cfb,  g_cfb);
    float* col_f  = (float*)p_col;
    float* cf_f   = (float*)p_cf;
    float* x_f    = (float*)p_x;
    float* h_f    = (float*)p_h;
    float* wr_f   = (float*)p_wr;
    float* pred_f = (float*)p_pred;
    float* cfb_f  = (float*)p_cfb;

    cudaFuncSetAttribute(k_mma_tf32,
                         cudaFuncAttributeMaxDynamicSharedMemorySize,
                         SMEM_GEMM_BYTES);
    cudaFuncSetAttribute(k_mma_w4,
                         cudaFuncAttributeMaxDynamicSharedMemorySize,
                         SMEM_W4_BYTES);

    // launch #1: all weight prep in one kernel
    k_prep<<<(PREP_TOTAL + 255)/256, 256>>>(w1, w2, w3, coef_w, freq_w,
                                            coef_b, freq_b);

    // launch #2: im2col (both images), tf32-rounded
    {
        const size_t total = (size_t)NIMG * NPIX * KCOL;
        k_im2col<<<(unsigned)((total + 255) / 256), 256>>>(feat);
    }

    // launch #3: SINGLE conv-as-GEMM over both images (M = 2*NPIX = 32768):
    // g_col is [img][pix][K] contiguous and g_cf is [img][pix][512]
    // contiguous, NPIX % 128 == 0 so no tile straddles the image boundary.
    k_mma_tf32<<<dim3(NCF/128, (NIMG*NPIX)/128), 256, SMEM_GEMM_BYTES>>>(
        col_f, wr_f + WR_CFW, cfb_f, cf_f,
        NIMG*NPIX, NCF, KCOL, 0);

    // launch #4: per-query assemble -> g_x rows (tf32-rounded)
    k_assemble<<<NQ, 256>>>(coord, cell, phase_w);

    // launches #5-#7: MLP layers 1,2 plain; layer 3 fused with W4
    k_mma_tf32<<<dim3(HD/128, NROWS/128), 256, SMEM_GEMM_BYTES>>>(
        x_f, wr_f + WR_W1, b1, h_f, NROWS, HD, HD, 3);
    k_mma_tf32<<<dim3(HD/128, NROWS/128), 256, SMEM_GEMM_BYTES>>>(
        h_f, wr_f + WR_W2, b2, x_f, NROWS, HD, HD, 3);
    k_mma_w4<<<dim3(2, NROWS/128), 256, SMEM_W4_BYTES>>>(
        x_f, wr_f + WR_W3, b3, w4, pred_f, HD);

    // launch #8: blend + bilinear + write out (light)
    k_finalize<<<(NIMG*NQ)/256, 256>>>(inp, coord, b4, out);
}

// round 15
// speedup vs baseline: 1.1948x; 1.0316x over previous
#include <cuda_runtime.h>
#include <cuda_bf16.h>
#include <cstdint>
#include <cstddef>

// ---------------------------------------------------------------------------
// Problem constants
// ---------------------------------------------------------------------------
#define NIMG   2
#define CIN    64
#define HF     128
#define WF     128
#define NPIX   (HF*WF)        // 16384
#define HD     256
#define KCOL   (CIN*9)        // 576
#define HO     256
#define WO     256
#define NQ     (HO*WO)        // 65536
#define NROWS  (NIMG*4*NQ)    // 524288
#define NCF    512            // merged coef|freq channel count

// ---------------------------------------------------------------------------
// Scratch (device globals; allocation-free)
// ---------------------------------------------------------------------------
__device__ float g_cf  [(size_t)NIMG*NPIX*NCF];    // NHWC coef|freq (fp32) 64MB
__device__ float g_x   [(size_t)NROWS*HD];         // activations
__device__ float g_h   [(size_t)NROWS*HD];         // activations
__device__ float g_area[(size_t)NROWS];
__device__ float g_pred[2][(size_t)NROWS*3];       // per-n-half partial preds
__device__ float g_wr  [3*HD*HD + 2*HD*KCOL];      // tf32-rounded weights
__device__ float g_cfb [NCF];                      // concat conv bias (raw)

#define WR_W1    0
#define WR_W2    (HD*HD)
#define WR_W3    (2*HD*HD)
#define WR_CFW   (3*HD*HD)            // [512][576]: rows 0-255 coef, 256-511 freq

__device__ __forceinline__ uint32_t f2tf32(float f)
{
    uint32_t r;
    asm("cvt.rna.tf32.f32 %0, %1;" : "=r"(r) : "f"(f));
    return r;
}
__device__ __forceinline__ float roundtf(float f)
{
    return __uint_as_float(f2tf32(f));
}
__device__ __forceinline__ void cp16(uint32_t dst, const void* src)
{
    asm volatile("cp.async.ca.shared.global [%0], [%1], 16;" :: "r"(dst), "l"(src));
}

// ---------------------------------------------------------------------------
// k_prep: tf32-round all 5 weight matrices + build concat conv bias.
// ---------------------------------------------------------------------------
#define PREP_TOTAL (3*HD*HD + 2*HD*KCOL + NCF)
__global__ void k_prep(const float* __restrict__ w1, const float* __restrict__ w2,
                       const float* __restrict__ w3, const float* __restrict__ cw,
                       const float* __restrict__ fw, const float* __restrict__ cb,
                       const float* __restrict__ fb)
{
    int i = blockIdx.x * blockDim.x + threadIdx.x;
    if (i >= PREP_TOTAL) return;
    if (i < 3*HD*HD + 2*HD*KCOL) {
        const float* src;
        int j = i;
        if (j < HD*HD)            { src = w1; }
        else if (j < 2*HD*HD)     { src = w2; j -= HD*HD; }
        else if (j < 3*HD*HD)     { src = w3; j -= 2*HD*HD; }
        else if (j < 3*HD*HD + HD*KCOL) { src = cw; j -= 3*HD*HD; }
        else                      { src = fw; j -= 3*HD*HD + HD*KCOL; }
        g_wr[i] = roundtf(src[j]);
    } else {
        int j = i - (3*HD*HD + 2*HD*KCOL);
        g_cfb[j] = (j < HD) ? cb[j] : fb[j - HD];
    }
}

// ---------------------------------------------------------------------------
// GEMM config (R12/R14-proven): BM=BN=128, BK=32, 256 threads, 8 warps (2x4),
// warp tile 64x32, mma m16n8k8, 2-stage cp.async double buffer.
// ---------------------------------------------------------------------------
#define BK     32
#define SMROW  36                      // 32 data + 4 pad; banks (4r+c)%32 unique
#define SMBUF  (128*SMROW)             // floats per buffer per matrix
#define SMEM_GEMM_BYTES (4 * SMBUF * 4)          // 73728 B
#define SMEM_W4_BYTES   (4 * SMBUF * 4 + 2048)   // + s_pred[128][4]

// Fragment compute for one BK=32 slab (4 ks rounds). Uses as/bs (uint32_t*),
// abase/bbase, acc.
#define GEMM_COMPUTE_SLAB                                                      \
        _Pragma("unroll")                                                      \
        for (int ks = 0; ks < 4; ks++) {                                       \
            uint32_t af[4][4], bf[4][2];                                       \
            _Pragma("unroll")                                                  \
            for (int mt = 0; mt < 4; mt++) {                                   \
                const int o = abase + mt*(16*SMROW) + ks*8;                    \
                af[mt][0] = as[o];                                             \
                af[mt][1] = as[o + 8*SMROW];                                   \
                af[mt][2] = as[o + 4];                                         \
                af[mt][3] = as[o + 8*SMROW + 4];                               \
            }                                                                  \
            _Pragma("unroll")                                                  \
            for (int nt = 0; nt < 4; nt++) {                                   \
                const int o = bbase + nt*(8*SMROW) + ks*8;                     \
                bf[nt][0] = bs[o];                                             \
                bf[nt][1] = bs[o + 4];                                         \
            }                                                                  \
            _Pragma("unroll")                                                  \
            for (int mt = 0; mt < 4; mt++)                                     \
                _Pragma("unroll")                                              \
                for (int nt = 0; nt < 4; nt++) {                               \
                    asm volatile(                                              \
                        "mma.sync.aligned.m16n8k8.row.col.f32.tf32.tf32.f32 "  \
                        "{%0,%1,%2,%3}, {%4,%5,%6,%7}, {%8,%9}, {%0,%1,%2,%3};\n" \
                        : "+f"(acc[mt][nt][0]), "+f"(acc[mt][nt][1]),          \
                          "+f"(acc[mt][nt][2]), "+f"(acc[mt][nt][3])           \
                        : "r"(af[mt][0]), "r"(af[mt][1]),                      \
                          "r"(af[mt][2]), "r"(af[mt][3]),                      \
                          "r"(bf[nt][0]), "r"(bf[nt][1]));                     \
                }                                                              \
        }

// Full mainloop for A,B both via cp.async (MLP layers).
#define GEMM_MAINLOOP(Kval)                                                    \
    const int row  = tid >> 1;                                                 \
    const int half = tid & 1;                                                  \
    const float* Ap = A + (size_t)(m0 + row) * (Kval) + half*16;               \
    const float* Bp = B + (size_t)(n0 + row) * (Kval) + half*16;               \
    const uint32_t sA0 = (uint32_t)__cvta_generic_to_shared(Asm)               \
                       + (row*SMROW + half*16)*4;                              \
    const uint32_t sB0 = (uint32_t)__cvta_generic_to_shared(Bsm)               \
                       + (row*SMROW + half*16)*4;                              \
    const uint32_t bufb = SMBUF * 4;                                           \
    const int abase = (wm*64 + (lane>>2)) * SMROW + (lane & 3);                \
    const int bbase = (wn*32 + (lane>>2)) * SMROW + (lane & 3);                \
    _Pragma("unroll")                                                          \
    for (int i = 0; i < 4; i++) cp16(sA0 + i*16, Ap + i*4);                    \
    _Pragma("unroll")                                                          \
    for (int i = 0; i < 4; i++) cp16(sB0 + i*16, Bp + i*4);                    \
    asm volatile("cp.async.commit_group;" ::: "memory");                       \
    const int nslab = (Kval) / BK;                                             \
    int buf = 0;                                                               \
    for (int s = 0; s < nslab; s++) {                                          \
        if (s + 1 < nslab) {                                                   \
            const int ko = (s + 1) * BK;                                       \
            const uint32_t bo = (uint32_t)(buf ^ 1) * bufb;                    \
            _Pragma("unroll")                                                  \
            for (int i = 0; i < 4; i++) cp16(sA0 + bo + i*16, Ap + ko + i*4);  \
            _Pragma("unroll")                                                  \
            for (int i = 0; i < 4; i++) cp16(sB0 + bo + i*16, Bp + ko + i*4);  \
            asm volatile("cp.async.commit_group;" ::: "memory");               \
            asm volatile("cp.async.wait_group 1;" ::: "memory");               \
        } else {                                                               \
            asm volatile("cp.async.wait_group 0;" ::: "memory");               \
        }                                                                      \
        __syncthreads();                                                       \
        const uint32_t* as = (const uint32_t*)(Asm + buf*SMBUF);               \
        const uint32_t* bs = (const uint32_t*)(Bsm + buf*SMBUF);               \
        GEMM_COMPUTE_SLAB                                                      \
        __syncthreads();                                                       \
        buf ^= 1;                                                              \
    }

// ---------------------------------------------------------------------------
// Plain GEMM (MLP layers 1,2): bias (+relu) (+tf32-round), store C.
// flags: bit0 = relu, bit1 = round output to tf32.
// ---------------------------------------------------------------------------
__global__ __launch_bounds__(256, 2)
void k_mma_tf32(const float* __restrict__ A, const float* __restrict__ B,
                const float* __restrict__ bias, float* __restrict__ C,
                int M, int N, int K, int flags)
{
    extern __shared__ float dynsmem[];
    float* Asm = dynsmem;
    float* Bsm = dynsmem + 2*SMBUF;

    const int tid  = threadIdx.x;
    const int warp = tid >> 5;
    const int lane = tid & 31;
    const int wm   = warp & 1;
    const int wn   = warp >> 1;
    const int m0 = blockIdx.y * 128;
    const int n0 = blockIdx.x * 128;

    float acc[4][4][4];
#pragma unroll
    for (int mt = 0; mt < 4; mt++)
#pragma unroll
        for (int nt = 0; nt < 4; nt++)
#pragma unroll
            for (int r = 0; r < 4; r++) acc[mt][nt][r] = 0.f;

    GEMM_MAINLOOP(K)

    const bool do_relu  = (flags & 1) != 0;
    const bool do_round = (flags & 2) != 0;
#pragma unroll
    for (int mt = 0; mt < 4; mt++) {
        const int rrow = m0 + wm*64 + mt*16 + (lane >> 2);
#pragma unroll
        for (int nt = 0; nt < 4; nt++) {
            const int col = n0 + wn*32 + nt*8 + 2*(lane & 3);
            const float bz0 = bias[col];
            const float bz1 = bias[col + 1];
            float v0 = acc[mt][nt][0] + bz0;
            float v1 = acc[mt][nt][1] + bz1;
            float v2 = acc[mt][nt][2] + bz0;
            float v3 = acc[mt][nt][3] + bz1;
            if (do_relu) {
                v0 = fmaxf(v0, 0.f); v1 = fmaxf(v1, 0.f);
                v2 = fmaxf(v2, 0.f); v3 = fmaxf(v3, 0.f);
            }
            if (do_round) {
                v0 = roundtf(v0); v1 = roundtf(v1);
                v2 = roundtf(v2); v3 = roundtf(v3);
            }
            *(float2*)(C + (size_t)rrow * N + col)       = make_float2(v0, v1);
            *(float2*)(C + (size_t)(rrow + 8) * N + col) = make_float2(v2, v3);
        }
    }
}

// ---------------------------------------------------------------------------
// Fused im2col + conv GEMM: M-tile = 128 pixels = one image row y0.
// A-tile col c of slab k0: k = k0+c -> (ic,ky,kx); value for x in [0,128) is
// feat[img][ic][y0+ky-1][x+kx-1] (0 outside), tf32-rounded — bit-identical to
// the old im2col + cp.async path. LDG issued before the B-wait to hide
// latency; STS after the barrier (prev consumer of buf^1 finished at the
// end-of-iter sync of s-1). B via cp.async as usual. N = NCF, K = KCOL.
// ---------------------------------------------------------------------------
__global__ __launch_bounds__(256, 2)
void k_conv(const float* __restrict__ feat, const float* __restrict__ B,
            const float* __restrict__ bias, float* __restrict__ C)
{
    extern __shared__ float dynsmem[];
    float* Asm = dynsmem;
    float* Bsm = dynsmem + 2*SMBUF;

    const int tid  = threadIdx.x;
    const int warp = tid >> 5;
    const int lane = tid & 31;
    const int wm   = warp & 1;
    const int wn   = warp >> 1;
    const int m0 = blockIdx.y * 128;
    const int n0 = blockIdx.x * 128;
    const int img = m0 >> 14;              // / NPIX
    const int y0  = (m0 & (NPIX - 1)) >> 7;

    // B cp.async mapping (2 threads per row, 4 x 16B)
    const int brow  = tid >> 1;
    const int bhalf = tid & 1;
    const float* Bp = B + (size_t)(n0 + brow) * KCOL + bhalf*16;
    const uint32_t sB0 = (uint32_t)__cvta_generic_to_shared(Bsm)
                       + (brow*SMROW + bhalf*16)*4;
    const uint32_t bufb = SMBUF * 4;

    // A loader mapping: col c = tid>>3, x = (tid&7) + 8*i
    const int ac  = tid >> 3;
    const int ax0 = tid & 7;

    const int abase = (wm*64 + (lane>>2)) * SMROW + (lane & 3);
    const int bbase = (wn*32 + (lane>>2)) * SMROW + (lane & 3);

    float acc[4][4][4];
#pragma unroll
    for (int mt = 0; mt < 4; mt++)
#pragma unroll
        for (int nt = 0; nt < 4; nt++)
#pragma unroll
            for (int r = 0; r < 4; r++) acc[mt][nt][r] = 0.f;

    // prologue: A slab 0 direct, B slab 0 cp.async
    {
        const int k  = ac;
        const int ic = k / 9, r9 = k - ic*9;
        const int ky = r9 / 3, kx = r9 - ky*3;
        const int gy = y0 + ky - 1;
        const bool yok = (unsigned)gy < (unsigned)HF;
        const float* frow = feat + (((size_t)img*CIN + ic)*HF + gy)*WF + (kx - 1);
#pragma unroll
        for (int i = 0; i < 16; i++) {
            const int x  = ax0 + 8*i;
            const int gx = x + kx - 1;
            float v = (yok && (unsigned)gx < (unsigned)WF) ? frow[x] : 0.f;
            Asm[x*SMROW + ac] = roundtf(v);
        }
#pragma unroll
        for (int i = 0; i < 4; i++) cp16(sB0 + i*16, Bp + i*4);
        asm volatile("cp.async.commit_group;" ::: "memory");
    }

    const int nslab = KCOL / BK;   // 18
    int buf = 0;
    for (int s = 0; s < nslab; s++) {
        const bool more = (s + 1) < nslab;

        // issue next-slab A LDGs early (into regs) to hide latency
        float av[16];
        if (more) {
            const int k  = (s + 1)*BK + ac;
            const int ic = k / 9, r9 = k - ic*9;
            const int ky = r9 / 3, kx = r9 - ky*3;
            const int gy = y0 + ky - 1;
            const bool yok = (unsigned)gy < (unsigned)HF;
            const float* frow = feat + (((size_t)img*CIN + ic)*HF + gy)*WF + (kx - 1);
#pragma unroll
            for (int i = 0; i < 16; i++) {
                const int x  = ax0 + 8*i;
                const int gx = x + kx - 1;
                av[i] = (yok && (unsigned)gx < (unsigned)WF) ? frow[x] : 0.f;
            }
        }

        if (more) {
            const int ko = (s + 1) * BK;
            const uint32_t bo = (uint32_t)(buf ^ 1) * bufb;
#pragma unroll
            for (int i = 0; i < 4; i++) cp16(sB0 + bo + i*16, Bp + ko + i*4);
            asm volatile("cp.async.commit_group;" ::: "memory");
            asm volatile("cp.async.wait_group 1;" ::: "memory");
        } else {
            asm volatile("cp.async.wait_group 0;" ::: "memory");
        }
        __syncthreads();

        if (more) {
            float* asn = Asm + (buf ^ 1)*SMBUF;
#pragma unroll
            for (int i = 0; i < 16; i++)
                asn[(ax0 + 8*i)*SMROW + ac] = roundtf(av[i]);
        }

        const uint32_t* as = (const uint32_t*)(Asm + buf*SMBUF);
        const uint32_t* bs = (const uint32_t*)(Bsm + buf*SMBUF);
        GEMM_COMPUTE_SLAB
        __syncthreads();
        buf ^= 1;
    }

    // epilogue: bias only (no relu, no round), N = NCF
#pragma unroll
    for (int mt = 0; mt < 4; mt++) {
        const int rrow = m0 + wm*64 + mt*16 + (lane >> 2);
#pragma unroll
        for (int nt = 0; nt < 4; nt++) {
            const int col = n0 + wn*32 + nt*8 + 2*(lane & 3);
            const float bz0 = bias[col];
            const float bz1 = bias[col + 1];
            *(float2*)(C + (size_t)rrow * NCF + col)
                = make_float2(acc[mt][nt][0] + bz0, acc[mt][nt][1] + bz1);
            *(float2*)(C + (size_t)(rrow + 8) * NCF + col)
                = make_float2(acc[mt][nt][2] + bz0, acc[mt][nt][3] + bz1);
        }
    }
}

// ---------------------------------------------------------------------------
// Layer-3 GEMM fused with W4: pred_half[c] = dot(relu(acc+bias), w4[c]) over
// this CTA's 128 columns; written to g_pred[blockIdx.x] (one writer per slot).
// grid = (2, NROWS/128); blockIdx.x selects the n-half.
// ---------------------------------------------------------------------------
__global__ __launch_bounds__(256, 2)
void k_mma_w4(const float* __restrict__ A, const float* __restrict__ B,
              const float* __restrict__ bias, const float* __restrict__ w4,
              float* __restrict__ pred_out, int K)
{
    extern __shared__ float dynsmem[];
    float* Asm    = dynsmem;
    float* Bsm    = dynsmem + 2*SMBUF;
    float* s_pred = dynsmem + 4*SMBUF;   // [128][4]

    const int tid  = threadIdx.x;
    const int warp = tid >> 5;
    const int lane = tid & 31;
    const int wm   = warp & 1;
    const int wn   = warp >> 1;
    const int m0 = blockIdx.y * 128;
    const int n0 = blockIdx.x * 128;

    for (int i = tid; i < 512; i += 256) s_pred[i] = 0.f;

    float acc[4][4][4];
#pragma unroll
    for (int mt = 0; mt < 4; mt++)
#pragma unroll
        for (int nt = 0; nt < 4; nt++)
#pragma unroll
            for (int r = 0; r < 4; r++) acc[mt][nt][r] = 0.f;

    GEMM_MAINLOOP(K)

#pragma unroll
    for (int mt = 0; mt < 4; mt++) {
        float p0[3] = {0.f, 0.f, 0.f};   // row r
        float p1[3] = {0.f, 0.f, 0.f};   // row r+8
#pragma unroll
        for (int nt = 0; nt < 4; nt++) {
#pragma unroll
            for (int e = 0; e < 2; e++) {
                const int col = n0 + wn*32 + nt*8 + 2*(lane & 3) + e;
                const float bz = bias[col];
                const float w40 = w4[col];
                const float w41 = w4[HD + col];
                const float w42 = w4[2*HD + col];
                float v0 = fmaxf(acc[mt][nt][e]     + bz, 0.f);
                float v1 = fmaxf(acc[mt][nt][2 + e] + bz, 0.f);
                p0[0] += v0*w40; p0[1] += v0*w41; p0[2] += v0*w42;
                p1[0] += v1*w40; p1[1] += v1*w41; p1[2] += v1*w42;
            }
        }
#pragma unroll
        for (int c = 0; c < 3; c++) {
            p0[c] += __shfl_xor_sync(0xffffffffu, p0[c], 1);
            p0[c] += __shfl_xor_sync(0xffffffffu, p0[c], 2);
            p1[c] += __shfl_xor_sync(0xffffffffu, p1[c], 1);
            p1[c] += __shfl_xor_sync(0xffffffffu, p1[c], 2);
        }
        if ((lane & 3) == 0) {
            const int lr0 = wm*64 + mt*16 + (lane >> 2);
#pragma unroll
            for (int c = 0; c < 3; c++) {
                atomicAdd(&s_pred[lr0*4 + c],       p0[c]);   // smem, 4 writers
                atomicAdd(&s_pred[(lr0 + 8)*4 + c], p1[c]);
            }
        }
    }
    __syncthreads();
    if (tid < 128) {
        float* gp = pred_out + (size_t)blockIdx.x * ((size_t)NROWS * 3)
                  + (size_t)(m0 + tid) * 3;
        gp[0] = s_pred[tid*4 + 0];
        gp[1] = s_pred[tid*4 + 1];
        gp[2] = s_pred[tid*4 + 2];
    }
}

// ---------------------------------------------------------------------------
// Assemble: one block per query q; builds all 8 rows (img, s) of g_x plus
// area. 32-bit offsets, hoisted per-q constants, shared pix between images.
// ---------------------------------------------------------------------------
__global__ __launch_bounds__(256)
void k_assemble(const float* __restrict__ coord, const float* __restrict__ cell,
                const float* __restrict__ phase_w)
{
    const int q  = blockIdx.x;
    const int t  = threadIdx.x & 127;
    const int hf = threadIdx.x >> 7;      // 0 = cos half, 1 = sin half

    const float cy = coord[2*q + 0];
    const float cx = coord[2*q + 1];
    const float rc0 = cell[2*q + 0] * 128.f;
    const float rc1 = cell[2*q + 1] * 128.f;
    const float ph  = rc0 * phase_w[2*t + 0] + rc1 * phase_w[2*t + 1];

    const unsigned fidx = (unsigned)(HD + 2*t);      // freq pair offset in row
    const unsigned cidx = (unsigned)(hf*128 + t);    // coef element offset
    const unsigned hoff = cidx;                      // g_x element offset

    const float RX  = 1.f / 128.f;
    const float EPS = 1e-6f;
    const float LO  = -1.0f + 1e-6f;
    const float HI  =  1.0f - 1e-6f;

#pragma unroll
    for (int s = 0; s < 4; s++) {
        const float vx = (s & 2) ? 1.f : -1.f;
        const float vy = (s & 1) ? 1.f : -1.f;

        float cys = fminf(fmaxf(cy + (vx*RX + EPS), LO), HI);
        float cxs = fminf(fmaxf(cx + (vy*RX + EPS), LO), HI);

        int iy = (int)rintf(((cys + 1.f)*128.f - 1.f)*0.5f);
        int ix = (int)rintf(((cxs + 1.f)*128.f - 1.f)*0.5f);
        iy = min(max(iy, 0), 127);
        ix = min(max(ix, 0), 127);

        const float qcy = -1.f + (1.f/128.f) + (2.f/128.f)*(float)iy;
        const float qcx = -1.f + (1.f/128.f) + (2.f/128.f)*(float)ix;
        const float rel0 = (cy - qcy) * 128.f;
        const float rel1 = (cx - qcx) * 128.f;

        if (threadIdx.x == 0) {
            const float ar = fabsf(rel0 * rel1) + 1e-9f;
            g_area[(unsigned)(s       << 16) + (unsigned)q] = ar;   // img 0
            g_area[(unsigned)((4 + s) << 16) + (unsigned)q] = ar;   // img 1
        }

        const unsigned pix = (unsigned)(iy * WF + ix);
        const float* cp0 = g_cf + (size_t)pix * NCF;         // img 0 row
        const float* cp1 = cp0 + (size_t)NPIX * NCF;         // img 1 row
        const unsigned ro0 = (((unsigned)s << 16) + (unsigned)q) << 8;
        const unsigned ro1 = ro0 + (1u << 26);               // img 1: +4*NQ*HD

        // img 0
        {
            const float qf = cp0[fidx] * rel0 + cp0[fidx + 1] * rel1 + ph;
            float sv, cv;
            __sincosf(3.14159265358979f * qf, &sv, &cv);
            g_x[ro0 + hoff] = roundtf(cp0[cidx] * (hf ? sv : cv));
        }
        // img 1
        {
            const float qf = cp1[fidx] * rel0 + cp1[fidx + 1] * rel1 + ph;
            float sv, cv;
            __sincosf(3.14159265358979f * qf, &sv, &cv);
            g_x[ro1 + hoff] = roundtf(cp1[cidx] * (hf ? sv : cv));
        }
    }
}

// ---------------------------------------------------------------------------
// Finalize (light): sum the two pred halves, blend (order [3,2,1,0]) + b4,
// bilinear-border of inp, write NCHW output. One thread per (img, q).
// ---------------------------------------------------------------------------
__global__ __launch_bounds__(256)
void k_finalize(const float* __restrict__ inp, const float* __restrict__ coord,
                const float* __restrict__ b4, float* __restrict__ out)
{
    const int gq = blockIdx.x * 256 + threadIdx.x;     // 0 .. 131071
    const int img = gq >> 16;
    const int q   = gq & (NQ - 1);

    float pred[4][3];
    float area[4];
#pragma unroll
    for (int s = 0; s < 4; s++) {
        const size_t rowi = ((size_t)(img*4 + s) << 16) + q;
        const float* gp0 = g_pred[0] + rowi * 3;
        const float* gp1 = g_pred[1] + rowi * 3;
        pred[s][0] = gp0[0] + gp1[0];
        pred[s][1] = gp0[1] + gp1[1];
        pred[s][2] = gp0[2] + gp1[2];
        area[s] = g_area[rowi];
    }

    const float tot = area[0] + area[1] + area[2] + area[3];
    const float w0 = area[3] / tot;   // order = [3,2,1,0]
    const float w1 = area[2] / tot;
    const float w2 = area[1] / tot;
    const float w3 = area[0] / tot;

    // bilinear (border clamp) on inp at coord
    const float cy = coord[2*q + 0];
    const float cx = coord[2*q + 1];
    float y = fminf(fmaxf(((cy + 1.f)*128.f - 1.f)*0.5f, 0.f), 127.f);
    float x = fminf(fmaxf(((cx + 1.f)*128.f - 1.f)*0.5f, 0.f), 127.f);
    float y0f = floorf(y), x0f = floorf(x);
    int y0 = (int)y0f, x0 = (int)x0f;
    float wy = y - y0f, wx = x - x0f;
    int y1 = min(y0 + 1, 127), x1 = min(x0 + 1, 127);

#pragma unroll
    for (int c = 0; c < 3; c++) {
        float ret = pred[0][c]*w0 + pred[1][c]*w1 + pred[2][c]*w2 + pred[3][c]*w3
                  + b4[c];
        const float* ip = inp + ((size_t)img*3 + c) * NPIX;
        float v00 = ip[y0*WF + x0];
        float v01 = ip[y0*WF + x1];
        float v10 = ip[y1*WF + x0];
        float v11 = ip[y1*WF + x1];
        float bv = v00*(1.f-wy)*(1.f-wx) + v01*(1.f-wy)*wx
                 + v10*wy*(1.f-wx)       + v11*wy*wx;
        out[(((size_t)img*3 + c) << 16) + q] = ret + bv;
    }
}

// ---------------------------------------------------------------------------
// Launch
// ---------------------------------------------------------------------------
extern "C" void kernel_launch(void* const* d_in, const int* in_sizes, int n_in,
                              void* d_out, int out_size)
{
    const float* feat    = (const float*)d_in[0];
    const float* inp     = (const float*)d_in[1];
    const float* coord   = (const float*)d_in[2];
    const float* cell    = (const float*)d_in[3];
    const float* coef_w  = (const float*)d_in[4];
    const float* coef_b  = (const float*)d_in[5];
    const float* freq_w  = (const float*)d_in[6];
    const float* freq_b  = (const float*)d_in[7];
    const float* phase_w = (const float*)d_in[8];
    const float* w1 = (const float*)d_in[9],  *b1 = (const float*)d_in[10];
    const float* w2 = (const float*)d_in[11], *b2 = (const float*)d_in[12];
    const float* w3 = (const float*)d_in[13], *b3 = (const float*)d_in[14];
    const float* w4 = (const float*)d_in[15], *b4 = (const float*)d_in[16];
    float* out = (float*)d_out;

    void *p_cf, *p_x, *p_h, *p_wr, *p_pred, *p_cfb;
    cudaGetSymbolAddress(&p_cf,   g_cf);
    cudaGetSymbolAddress(&p_x,    g_x);
    cudaGetSymbolAddress(&p_h,    g_h);
    cudaGetSymbolAddress(&p_wr,   g_wr);
    cudaGetSymbolAddress(&p_pred, g_pred);
    cudaGetSymbolAddress(&p_cfb,  g_cfb);
    float* cf_f   = (float*)p_cf;
    float* x_f    = (float*)p_x;
    float* h_f    = (float*)p_h;
    float* wr_f   = (float*)p_wr;
    float* pred_f = (float*)p_pred;
    float* cfb_f  = (float*)p_cfb;

    cudaFuncSetAttribute(k_mma_tf32,
                         cudaFuncAttributeMaxDynamicSharedMemorySize,
                         SMEM_GEMM_BYTES);
    cudaFuncSetAttribute(k_conv,
                         cudaFuncAttributeMaxDynamicSharedMemorySize,
                         SMEM_GEMM_BYTES);
    cudaFuncSetAttribute(k_mma_w4,
                         cudaFuncAttributeMaxDynamicSharedMemorySize,
                         SMEM_W4_BYTES);

    // launch #1: weight prep
    k_prep<<<(PREP_TOTAL + 255)/256, 256>>>(w1, w2, w3, coef_w, freq_w,
                                            coef_b, freq_b);

    // launch #2: fused im2col + conv GEMM over both images (M = 32768)
    k_conv<<<dim3(NCF/128, (NIMG*NPIX)/128), 256, SMEM_GEMM_BYTES>>>(
        feat, wr_f + WR_CFW, cfb_f, cf_f);

    // launch #3: per-query assemble -> g_x rows (tf32-rounded)
    k_assemble<<<NQ, 256>>>(coord, cell, phase_w);

    // launches #4-#6: MLP layers 1,2 plain; layer 3 fused with W4
    k_mma_tf32<<<dim3(HD/128, NROWS/128), 256, SMEM_GEMM_BYTES>>>(
        x_f, wr_f + WR_W1, b1, h_f, NROWS, HD, HD, 3);
    k_mma_tf32<<<dim3(HD/128, NROWS/128), 256, SMEM_GEMM_BYTES>>>(
        h_f, wr_f + WR_W2, b2, x_f, NROWS, HD, HD, 3);
    k_mma_w4<<<dim3(2, NROWS/128), 256, SMEM_W4_BYTES>>>(
        x_f, wr_f + WR_W3, b3, w4, pred_f, HD);

    // launch #7: blend + bilinear + write out (light)
    k_finalize<<<(NIMG*NQ)/256, 256>>>(inp, coord, b4, out);
}